// round 1
// baseline (speedup 1.0000x reference)
#include <cuda_runtime.h>
#include <cstdint>

// Problem dims (fixed by the reference):
//   x:         [2, 1024, 4096] fp32  -> A [M=2048, K=4096]
//   codebooks: [4096, 32, 16]  fp32
//   codes:     [4096, 32, 128] int32 (values 0..15)
//   bias:      [4096]          fp32
//   out:       [2, 1024, 4096] fp32  -> C [M=2048, N=4096]
// C = A @ W^T + bias, W[n,k] = codebooks[n, k/128, codes[n, k/128, k%128]]

constexpr int KDIM = 4096;
constexpr int NDIM = 4096;
constexpr int MDIM = 2048;

// Scratch for dequantized weights (allocation-free rule: __device__ global).
__device__ float g_W[(size_t)NDIM * KDIM];

// ---------------------------------------------------------------------------
// Phase 1: dequantize one row per block. codes row = 4096 int32, codebook row
// = 32 groups x 16 floats (2KB, staged in smem).
// ---------------------------------------------------------------------------
__global__ void dequant_kernel(const float* __restrict__ codebooks,
                               const int* __restrict__ codes) {
    const int r = blockIdx.x;
    __shared__ float cb[512];
    const float* cbr = codebooks + (size_t)r * 512;
    for (int i = threadIdx.x; i < 512; i += 256) cb[i] = cbr[i];
    __syncthreads();

    const int4* codes_r = (const int4*)(codes + (size_t)r * KDIM);
    float4* w_r = (float4*)(g_W + (size_t)r * KDIM);
    #pragma unroll
    for (int it = 0; it < 4; it++) {
        int i = threadIdx.x + it * 256;          // i indexes int4 chunks (4 elems)
        int4 c = codes_r[i];
        const float* cbg = cb + ((i >> 5) << 4); // group = (4*i)/128 = i/32
        w_r[i] = make_float4(cbg[c.x], cbg[c.y], cbg[c.z], cbg[c.w]);
    }
}

// ---------------------------------------------------------------------------
// Phase 2: SIMT fp32 GEMM, NT layout (both A and W are K-major).
// Block tile 128x128, K-tile 16, 256 threads, 8x8 micro-tile per thread.
// Global loads register-prefetched one K-tile ahead to hide DRAM/L2 latency
// behind the FMA stream.
// ---------------------------------------------------------------------------
constexpr int BM = 128, BN = 128, BK = 16;

__global__ __launch_bounds__(256, 2)
void gemm_kernel(const float* __restrict__ A,
                 const float* __restrict__ bias,
                 float* __restrict__ C) {
    __shared__ float As[BK][BM];
    __shared__ float Bs[BK][BN];

    const int tid = threadIdx.x;
    const int m0 = blockIdx.y * BM;
    const int n0 = blockIdx.x * BN;

    // compute mapping: 16x16 thread grid, 8x8 outputs each
    const int tm = (tid >> 4) * 8;
    const int tn = (tid & 15) * 8;

    // load mapping: 64 rows x 4 float4-cols per pass, two passes (rows +64)
    const int lrow = tid >> 2;
    const int lcol = (tid & 3) * 4;

    const float* Ab = A + (size_t)(m0 + lrow) * KDIM + lcol;
    const float* Bb = g_W + (size_t)(n0 + lrow) * KDIM + lcol;

    // prefetch K-tile 0
    float4 a0 = *(const float4*)(Ab);
    float4 a1 = *(const float4*)(Ab + (size_t)64 * KDIM);
    float4 b0 = *(const float4*)(Bb);
    float4 b1 = *(const float4*)(Bb + (size_t)64 * KDIM);

    float acc[8][8] = {};

    for (int k0 = 0; k0 < KDIM; k0 += BK) {
        // commit prefetched tile to smem (transposed: As[k][m], Bs[k][n])
        As[lcol + 0][lrow]      = a0.x; As[lcol + 1][lrow]      = a0.y;
        As[lcol + 2][lrow]      = a0.z; As[lcol + 3][lrow]      = a0.w;
        As[lcol + 0][lrow + 64] = a1.x; As[lcol + 1][lrow + 64] = a1.y;
        As[lcol + 2][lrow + 64] = a1.z; As[lcol + 3][lrow + 64] = a1.w;
        Bs[lcol + 0][lrow]      = b0.x; Bs[lcol + 1][lrow]      = b0.y;
        Bs[lcol + 2][lrow]      = b0.z; Bs[lcol + 3][lrow]      = b0.w;
        Bs[lcol + 0][lrow + 64] = b1.x; Bs[lcol + 1][lrow + 64] = b1.y;
        Bs[lcol + 2][lrow + 64] = b1.z; Bs[lcol + 3][lrow + 64] = b1.w;
        __syncthreads();

        // prefetch next K-tile while computing this one
        if (k0 + BK < KDIM) {
            a0 = *(const float4*)(Ab + k0 + BK);
            a1 = *(const float4*)(Ab + (size_t)64 * KDIM + k0 + BK);
            b0 = *(const float4*)(Bb + k0 + BK);
            b1 = *(const float4*)(Bb + (size_t)64 * KDIM + k0 + BK);
        }

        #pragma unroll
        for (int kk = 0; kk < BK; kk++) {
            float a[8], b[8];
            *(float4*)(a)     = *(const float4*)&As[kk][tm];
            *(float4*)(a + 4) = *(const float4*)&As[kk][tm + 4];
            *(float4*)(b)     = *(const float4*)&Bs[kk][tn];
            *(float4*)(b + 4) = *(const float4*)&Bs[kk][tn + 4];
            #pragma unroll
            for (int i = 0; i < 8; i++)
                #pragma unroll
                for (int j = 0; j < 8; j++)
                    acc[i][j] += a[i] * b[j];
        }
        __syncthreads();
    }

    // epilogue: add bias, vectorized stores
    float bj[8];
    *(float4*)(bj)     = *(const float4*)(bias + n0 + tn);
    *(float4*)(bj + 4) = *(const float4*)(bias + n0 + tn + 4);
    #pragma unroll
    for (int i = 0; i < 8; i++) {
        float* crow = C + (size_t)(m0 + tm + i) * NDIM + n0 + tn;
        float4 o0 = make_float4(acc[i][0] + bj[0], acc[i][1] + bj[1],
                                acc[i][2] + bj[2], acc[i][3] + bj[3]);
        float4 o1 = make_float4(acc[i][4] + bj[4], acc[i][5] + bj[5],
                                acc[i][6] + bj[6], acc[i][7] + bj[7]);
        *(float4*)(crow)     = o0;
        *(float4*)(crow + 4) = o1;
    }
}

// ---------------------------------------------------------------------------
extern "C" void kernel_launch(void* const* d_in, const int* in_sizes, int n_in,
                              void* d_out, int out_size) {
    const float* x         = (const float*)d_in[0];
    const float* codebooks = (const float*)d_in[1];
    const int*   codes     = (const int*)d_in[2];
    const float* bias      = (const float*)d_in[3];
    float* out = (float*)d_out;

    dequant_kernel<<<NDIM, 256>>>(codebooks, codes);

    dim3 grid(NDIM / BN, MDIM / BM);
    gemm_kernel<<<grid, 256>>>(x, bias, out);
}

// round 3
// speedup vs baseline: 3.5572x; 3.5572x over previous
#include <cuda_runtime.h>
#include <cstdint>

// C[2048,4096] = A[2048,4096] @ W[4096,4096]^T + bias
// W dequantized from 4-bit codebook codes.
// GEMM via warp-level mma.sync tf32 (sm_103-compatible PTX; tcgen05 is
// 'a'-feature-gated and rejected by this harness's compute_103 PTX target).

constexpr int KDIM = 4096;
constexpr int NDIM = 4096;
constexpr int MDIM = 2048;

__device__ float g_W[(size_t)NDIM * KDIM];   // dequantized, tf32-rounded
__device__ float g_A[(size_t)MDIM * KDIM];   // activations, tf32-rounded

__device__ __forceinline__ float to_tf32(float v) {
    uint32_t b;
    asm("cvt.rna.tf32.f32 %0, %1;" : "=r"(b) : "f"(v));
    return __uint_as_float(b);
}

// ---------------------------------------------------------------------------
// Phase 1a: dequantize W (one row per block), store tf32-rounded.
// ---------------------------------------------------------------------------
__global__ void dequant_kernel(const float* __restrict__ codebooks,
                               const int* __restrict__ codes) {
    const int r = blockIdx.x;
    __shared__ float cb[512];
    const float* cbr = codebooks + (size_t)r * 512;
    for (int i = threadIdx.x; i < 512; i += 256) cb[i] = cbr[i];
    __syncthreads();

    const int4* codes_r = (const int4*)(codes + (size_t)r * KDIM);
    float4* w_r = (float4*)(g_W + (size_t)r * KDIM);
    #pragma unroll
    for (int it = 0; it < 4; it++) {
        int i = threadIdx.x + it * 256;
        int4 c = codes_r[i];
        const float* cbg = cb + ((i >> 5) << 4);
        w_r[i] = make_float4(to_tf32(cbg[c.x]), to_tf32(cbg[c.y]),
                             to_tf32(cbg[c.z]), to_tf32(cbg[c.w]));
    }
}

// ---------------------------------------------------------------------------
// Phase 1b: round A to tf32.
// ---------------------------------------------------------------------------
__global__ void aconv_kernel(const float* __restrict__ x) {
    size_t i = ((size_t)blockIdx.x * 256 + threadIdx.x);
    const float4 v = ((const float4*)x)[i];
    ((float4*)g_A)[i] = make_float4(to_tf32(v.x), to_tf32(v.y),
                                    to_tf32(v.z), to_tf32(v.w));
}

// ---------------------------------------------------------------------------
// Phase 2: tf32 mma.sync GEMM. Block 128x256x32, 8 warps, warp tile 64x64.
// Smem rows padded to stride 36 floats -> conflict-free fragment loads.
// ---------------------------------------------------------------------------
constexpr int BM = 128, BN = 256, BK = 32;
constexpr int STRIDE = BK + 4;                       // 36 floats
constexpr int A_STAGE = BM * STRIDE;                 // 4608 floats
constexpr int B_STAGE = BN * STRIDE;                 // 9216 floats
constexpr int STAGE   = A_STAGE + B_STAGE;           // 13824 floats
constexpr int SMEM_DYN = STAGE * 2 * 4;              // 110592 bytes
constexpr int KITERS = KDIM / BK;                    // 128

extern __shared__ float smf[];

__device__ __forceinline__ uint32_t smem_u32(const void* p) {
    uint32_t a;
    asm("{ .reg .u64 t; cvta.to.shared.u64 t, %1; cvt.u32.u64 %0, t; }"
        : "=r"(a) : "l"(p));
    return a;
}

__device__ __forceinline__ void cp_async16(uint32_t dst, const void* src) {
    asm volatile("cp.async.cg.shared.global [%0], [%1], 16;"
                 :: "r"(dst), "l"(src));
}

__device__ __forceinline__ void mma_tf32(float* c, const uint32_t* a,
                                         const uint32_t* b) {
    asm volatile(
        "mma.sync.aligned.m16n8k8.row.col.f32.tf32.tf32.f32 "
        "{%0,%1,%2,%3}, {%4,%5,%6,%7}, {%8,%9}, {%0,%1,%2,%3};"
        : "+f"(c[0]), "+f"(c[1]), "+f"(c[2]), "+f"(c[3])
        : "r"(a[0]), "r"(a[1]), "r"(a[2]), "r"(a[3]), "r"(b[0]), "r"(b[1]));
}

__device__ __forceinline__ void load_tile(uint32_t sbase,
                                          const float* __restrict__ Ab,
                                          const float* __restrict__ Bb,
                                          int k0, int tid) {
    // A: 128 rows x 8 float4; 1024 chunks, 4/thread
    #pragma unroll
    for (int j = 0; j < 4; j++) {
        int i = tid + j * 256;
        int row = i >> 3, ci = (i & 7) * 4;
        cp_async16(sbase + (uint32_t)(row * STRIDE + ci) * 4,
                   Ab + (size_t)row * KDIM + k0 + ci);
    }
    // B: 256 rows x 8 float4; 2048 chunks, 8/thread
    const uint32_t sb = sbase + A_STAGE * 4;
    #pragma unroll
    for (int j = 0; j < 8; j++) {
        int i = tid + j * 256;
        int row = i >> 3, ci = (i & 7) * 4;
        cp_async16(sb + (uint32_t)(row * STRIDE + ci) * 4,
                   Bb + (size_t)row * KDIM + k0 + ci);
    }
    asm volatile("cp.async.commit_group;" ::: "memory");
}

__global__ void __launch_bounds__(256, 1)
gemm_mma_kernel(const float* __restrict__ bias, float* __restrict__ C) {
    const int tid  = threadIdx.x;
    const int wid  = tid >> 5;
    const int lane = tid & 31;
    const int gid  = lane >> 2;      // group of 4
    const int tig  = lane & 3;       // thread in group

    const int m0 = blockIdx.y * BM;
    const int n0 = blockIdx.x * BN;
    const int wm = (wid >> 2) * 64;  // warp grid 2(M) x 4(N), tile 64x64
    const int wn = (wid & 3) * 64;

    const uint32_t smem_base = smem_u32(smf);
    const float* Ab = g_A + (size_t)m0 * KDIM;
    const float* Bb = g_W + (size_t)n0 * KDIM;

    float acc[4][8][4] = {};

    load_tile(smem_base, Ab, Bb, 0, tid);

    for (int it = 0; it < KITERS; it++) {
        if (it + 1 < KITERS) {
            load_tile(smem_base + ((it + 1) & 1) * STAGE * 4,
                      Ab, Bb, (it + 1) * BK, tid);
            asm volatile("cp.async.wait_group 1;" ::: "memory");
        } else {
            asm volatile("cp.async.wait_group 0;" ::: "memory");
        }
        __syncthreads();

        const float* sA = smf + (it & 1) * STAGE;
        const float* sB = sA + A_STAGE;

        #pragma unroll
        for (int ks = 0; ks < 4; ks++) {
            const int kb = ks * 8;
            uint32_t af[4][4], bf[8][2];
            #pragma unroll
            for (int mt = 0; mt < 4; mt++) {
                const float* p = sA + (wm + mt * 16 + gid) * STRIDE + kb + tig;
                af[mt][0] = __float_as_uint(p[0]);
                af[mt][1] = __float_as_uint(p[8 * STRIDE]);
                af[mt][2] = __float_as_uint(p[4]);
                af[mt][3] = __float_as_uint(p[8 * STRIDE + 4]);
            }
            #pragma unroll
            for (int nt = 0; nt < 8; nt++) {
                const float* p = sB + (wn + nt * 8 + gid) * STRIDE + kb + tig;
                bf[nt][0] = __float_as_uint(p[0]);
                bf[nt][1] = __float_as_uint(p[4]);
            }
            #pragma unroll
            for (int mt = 0; mt < 4; mt++)
                #pragma unroll
                for (int nt = 0; nt < 8; nt++)
                    mma_tf32(acc[mt][nt], af[mt], bf[nt]);
        }
        __syncthreads();
    }

    // epilogue: bias + store (float2 per fragment row)
    #pragma unroll
    for (int mt = 0; mt < 4; mt++) {
        #pragma unroll
        for (int nt = 0; nt < 8; nt++) {
            const int r0 = m0 + wm + mt * 16 + gid;
            const int c  = n0 + wn + nt * 8 + tig * 2;
            const float2 b2 = *(const float2*)(bias + c);
            float2 o0, o1;
            o0.x = acc[mt][nt][0] + b2.x;
            o0.y = acc[mt][nt][1] + b2.y;
            o1.x = acc[mt][nt][2] + b2.x;
            o1.y = acc[mt][nt][3] + b2.y;
            *(float2*)(C + (size_t)r0 * NDIM + c)       = o0;
            *(float2*)(C + (size_t)(r0 + 8) * NDIM + c) = o1;
        }
    }
}

// ---------------------------------------------------------------------------
extern "C" void kernel_launch(void* const* d_in, const int* in_sizes, int n_in,
                              void* d_out, int out_size) {
    const float* x         = (const float*)d_in[0];
    const float* codebooks = (const float*)d_in[1];
    const int*   codes     = (const int*)d_in[2];
    const float* bias      = (const float*)d_in[3];
    float* out = (float*)d_out;

    dequant_kernel<<<NDIM, 256>>>(codebooks, codes);
    aconv_kernel<<<(MDIM * KDIM / 4) / 256, 256>>>(x);

    cudaFuncSetAttribute(gemm_mma_kernel,
                         cudaFuncAttributeMaxDynamicSharedMemorySize, SMEM_DYN);
    dim3 grid(NDIM / BN, MDIM / BM);   // (16, 16)
    gemm_mma_kernel<<<grid, 256, SMEM_DYN>>>(bias, out);
}